// round 1
// baseline (speedup 1.0000x reference)
#include <cuda_runtime.h>

#define HIDDEN 64
#define N_LAYERS 4
#define BN_EPS 1e-5f
#define MAX_NODES 100000

// Scratch: reused as agg -> u -> h_next per layer. 25.6 MB.
__device__ __align__(16) float g_scratch[MAX_NODES * HIDDEN];
// Per-layer batch-norm stats: [layer][0:64]=colsum, [layer][64:128]=colsumsq
__device__ float g_stats[N_LAYERS * 128];

// ---------------------------------------------------------------------------
// Init: h = node_feat, scratch = node_feat, zero all stats.
// ---------------------------------------------------------------------------
__global__ void init_kernel(float4* __restrict__ h,
                            const float4* __restrict__ node,
                            int n4) {
    int i = blockIdx.x * blockDim.x + threadIdx.x;
    if (i < N_LAYERS * 128) g_stats[i] = 0.f;
    if (i < n4) {
        float4 v = node[i];
        h[i] = v;
        reinterpret_cast<float4*>(g_scratch)[i] = v;
    }
}

// ---------------------------------------------------------------------------
// Edge scatter: for each edge, msg = relu(h[src] + edge_feat@We + be),
// atomically add into scratch (which holds h, so scratch becomes z = h+agg).
// 16 threads per edge, each handles one float4 of the 64-wide row.
// ---------------------------------------------------------------------------
__global__ void edge_kernel(const float* __restrict__ h,
                            const float4* __restrict__ ef,
                            const int* __restrict__ src,
                            const int* __restrict__ dst,
                            const float* __restrict__ We,
                            const float* __restrict__ be,
                            int nE) {
    __shared__ float4 Wes[4][16];   // We[k][j], float4-grouped over j
    __shared__ float4 bes[16];
    int t = threadIdx.x;
    if (t < 256) reinterpret_cast<float*>(Wes)[t] = We[t];
    if (t < 64)  reinterpret_cast<float*>(bes)[t] = be[t];
    __syncthreads();

    int gid = blockIdx.x * blockDim.x + t;
    int edge = gid >> 4;
    if (edge >= nE) return;
    int lane = gid & 15;

    float4 e4 = ef[edge];                  // same addr for 16 lanes -> coalesced bcast
    int s = src[edge];
    int d = dst[edge];
    float4 hv = *reinterpret_cast<const float4*>(h + s * HIDDEN + lane * 4);

    float4 w0 = Wes[0][lane], w1 = Wes[1][lane], w2 = Wes[2][lane], w3 = Wes[3][lane];
    float4 b  = bes[lane];

    float4 m;
    m.x = fmaxf(hv.x + b.x + e4.x * w0.x + e4.y * w1.x + e4.z * w2.x + e4.w * w3.x, 0.f);
    m.y = fmaxf(hv.y + b.y + e4.x * w0.y + e4.y * w1.y + e4.z * w2.y + e4.w * w3.y, 0.f);
    m.z = fmaxf(hv.z + b.z + e4.x * w0.z + e4.y * w1.z + e4.z * w2.z + e4.w * w3.z, 0.f);
    m.w = fmaxf(hv.w + b.w + e4.x * w0.w + e4.y * w1.w + e4.z * w2.w + e4.w * w3.w, 0.f);

    float* ap = g_scratch + d * HIDDEN + lane * 4;
    asm volatile("red.global.add.v4.f32 [%0], {%1, %2, %3, %4};"
                 :: "l"(ap), "f"(m.x), "f"(m.y), "f"(m.z), "f"(m.w)
                 : "memory");
}

// ---------------------------------------------------------------------------
// MLP: u = relu(z@W1 + b1)@W2 + b2, z read from scratch, u written back.
// One 64-thread block handles 64 rows (thread = row). Weights + z tile staged
// in shared (z tile padded to 65 floats/row for conflict-free column access).
// Fuses batch-stat partial reduction (block colsum/colsumsq -> global atomics).
// ---------------------------------------------------------------------------
__global__ __launch_bounds__(64) void mlp_kernel(const float* __restrict__ W1,
                                                 const float* __restrict__ b1,
                                                 const float* __restrict__ W2,
                                                 const float* __restrict__ b2,
                                                 int layer, int n) {
    __shared__ float Ws[64 * 64];
    __shared__ float Zs[64 * 65];
    __shared__ float bs[64];
    int t = threadIdx.x;
    int row0 = blockIdx.x * 64;
    const float4* W1l4 = reinterpret_cast<const float4*>(W1 + layer * 4096);
    const float4* W2l4 = reinterpret_cast<const float4*>(W2 + layer * 4096);
    float4* Ws4 = reinterpret_cast<float4*>(Ws);

    // Stage W1 + b1 + z tile
    #pragma unroll
    for (int i = 0; i < 16; i++) Ws4[i * 64 + t] = W1l4[i * 64 + t];
    bs[t] = b1[layer * 64 + t];
    for (int r = 0; r < 64; r++) {
        int rr = row0 + r;
        Zs[r * 65 + t] = (rr < n) ? g_scratch[rr * HIDDEN + t] : 0.f;
    }
    __syncthreads();

    bool valid = (row0 + t) < n;
    float acc[64];
    #pragma unroll
    for (int j = 0; j < 64; j++) acc[j] = bs[j];

    // Phase 1: t = relu(z @ W1 + b1)
    for (int k = 0; k < 64; k++) {
        float zk = Zs[t * 65 + k];
        const float4* wr = reinterpret_cast<const float4*>(Ws + k * 64);
        #pragma unroll
        for (int j = 0; j < 16; j++) {
            float4 w = wr[j];
            acc[4 * j + 0] += zk * w.x;
            acc[4 * j + 1] += zk * w.y;
            acc[4 * j + 2] += zk * w.z;
            acc[4 * j + 3] += zk * w.w;
        }
    }
    // Write relu(t) back into own z row (only self reads it -> no sync needed)
    #pragma unroll
    for (int j = 0; j < 64; j++) Zs[t * 65 + j] = fmaxf(acc[j], 0.f);

    __syncthreads();
    // Stage W2 + b2
    #pragma unroll
    for (int i = 0; i < 16; i++) Ws4[i * 64 + t] = W2l4[i * 64 + t];
    bs[t] = b2[layer * 64 + t];
    __syncthreads();

    #pragma unroll
    for (int j = 0; j < 64; j++) acc[j] = bs[j];

    // Phase 2: u = t @ W2 + b2
    for (int k = 0; k < 64; k++) {
        float tk = Zs[t * 65 + k];
        const float4* wr = reinterpret_cast<const float4*>(Ws + k * 64);
        #pragma unroll
        for (int j = 0; j < 16; j++) {
            float4 w = wr[j];
            acc[4 * j + 0] += tk * w.x;
            acc[4 * j + 1] += tk * w.y;
            acc[4 * j + 2] += tk * w.z;
            acc[4 * j + 3] += tk * w.w;
        }
    }
    __syncthreads();   // everyone done reading Zs (phase-2 t values)

    // Put u into own Zs row (zeros for invalid rows so stats stay clean)
    #pragma unroll
    for (int j = 0; j < 64; j++) Zs[t * 65 + j] = valid ? acc[j] : 0.f;
    __syncthreads();

    // Coalesced store of u to scratch
    for (int r = 0; r < 64; r++) {
        int rr = row0 + r;
        if (rr < n) g_scratch[rr * HIDDEN + t] = Zs[r * 65 + t];
    }

    // Block-level column stats, one atomic pair per column per block
    float s = 0.f, sq = 0.f;
    for (int r = 0; r < 64; r++) {
        float v = Zs[r * 65 + t];
        s += v;
        sq += v * v;
    }
    atomicAdd(&g_stats[layer * 128 + t], s);
    atomicAdd(&g_stats[layer * 128 + 64 + t], sq);
}

// ---------------------------------------------------------------------------
// BN + ReLU + residual: h = relu(gamma*(u-mu)*istd + beta) + h.
// Writes h (d_out) in place; also refreshes scratch = h_new for the next
// layer's aggregation (skipped on last layer).
// ---------------------------------------------------------------------------
__global__ void bn_kernel(float4* __restrict__ h,
                          const float* __restrict__ gamma,
                          const float* __restrict__ beta,
                          int layer, int n4, float invN, int last) {
    int i = blockIdx.x * blockDim.x + threadIdx.x;
    if (i >= n4) return;
    int j = (i & 15) * 4;
    const float* st = g_stats + layer * 128;
    const float* g  = gamma + layer * 64;
    const float* be = beta + layer * 64;

    float4 u  = reinterpret_cast<const float4*>(g_scratch)[i];
    float4 hv = h[i];
    float4 r;

    #define BN_COMP(comp, jj)                                              \
    {                                                                      \
        float mu  = st[jj] * invN;                                         \
        float var = st[64 + jj] * invN - mu * mu;                          \
        float z   = g[jj] * (u.comp - mu) * rsqrtf(var + BN_EPS) + be[jj]; \
        r.comp    = fmaxf(z, 0.f) + hv.comp;                               \
    }
    BN_COMP(x, j + 0)
    BN_COMP(y, j + 1)
    BN_COMP(z, j + 2)
    BN_COMP(w, j + 3)
    #undef BN_COMP

    h[i] = r;
    if (!last) reinterpret_cast<float4*>(g_scratch)[i] = r;
}

// ---------------------------------------------------------------------------
extern "C" void kernel_launch(void* const* d_in, const int* in_sizes, int n_in,
                              void* d_out, int out_size) {
    const float*  node  = (const float*)d_in[0];
    const float4* ef    = (const float4*)d_in[1];
    const int*    src   = (const int*)d_in[2];
    const int*    dst   = (const int*)d_in[3];
    const float*  We    = (const float*)d_in[4];
    const float*  be    = (const float*)d_in[5];
    const float*  W1    = (const float*)d_in[6];
    const float*  b1    = (const float*)d_in[7];
    const float*  W2    = (const float*)d_in[8];
    const float*  b2    = (const float*)d_in[9];
    const float*  gamma = (const float*)d_in[10];
    const float*  beta  = (const float*)d_in[11];

    float* h = (float*)d_out;
    int n  = in_sizes[0] / HIDDEN;   // 100000
    int nE = in_sizes[2];            // 1600000
    int n4 = n * (HIDDEN / 4);
    float invN = 1.f / (float)n;

    init_kernel<<<(n4 + 255) / 256, 256>>>((float4*)h, (const float4*)node, n4);

    for (int l = 0; l < N_LAYERS; l++) {
        int egrid = (nE * 16 + 255) / 256;
        edge_kernel<<<egrid, 256>>>(h, ef, src, dst, We, be, nE);
        mlp_kernel<<<(n + 63) / 64, 64>>>(W1, b1, W2, b2, l, n);
        bn_kernel<<<(n4 + 255) / 256, 256>>>((float4*)h, gamma, beta, l, n4,
                                             invN, l == N_LAYERS - 1);
    }
}

// round 2
// speedup vs baseline: 1.0294x; 1.0294x over previous
#include <cuda_runtime.h>

#define HIDDEN 64
#define N_LAYERS 4
#define BN_EPS 1e-5f
#define MAX_NODES 100000

// Scratch: reused as agg -> u -> h_next per layer. 25.6 MB.
__device__ __align__(16) float g_scratch[MAX_NODES * HIDDEN];
// Per-layer batch-norm stats: [layer][0:64]=colsum, [layer][64:128]=colsumsq
__device__ float g_stats[N_LAYERS * 128];

// ---------------------------------------------------------------------------
// Init: h = node_feat, scratch = node_feat, zero all stats.
// ---------------------------------------------------------------------------
__global__ void init_kernel(float4* __restrict__ h,
                            const float4* __restrict__ node,
                            int n4) {
    int i = blockIdx.x * blockDim.x + threadIdx.x;
    if (i < N_LAYERS * 128) g_stats[i] = 0.f;
    if (i < n4) {
        float4 v = node[i];
        h[i] = v;
        reinterpret_cast<float4*>(g_scratch)[i] = v;
    }
}

// ---------------------------------------------------------------------------
// Edge scatter: for each edge, msg = relu(h[src] + edge_feat@We + be),
// atomically add into scratch (which holds h, so scratch becomes z = h+agg).
// 16 threads per edge, each handles one float4 of the 64-wide row.
// ---------------------------------------------------------------------------
__global__ void edge_kernel(const float* __restrict__ h,
                            const float4* __restrict__ ef,
                            const int* __restrict__ src,
                            const int* __restrict__ dst,
                            const float* __restrict__ We,
                            const float* __restrict__ be,
                            int nE) {
    __shared__ float4 Wes[4][16];   // We[k][j], float4-grouped over j
    __shared__ float4 bes[16];
    int t = threadIdx.x;
    if (t < 256) reinterpret_cast<float*>(Wes)[t] = We[t];
    if (t < 64)  reinterpret_cast<float*>(bes)[t] = be[t];
    __syncthreads();

    int gid = blockIdx.x * blockDim.x + t;
    int edge = gid >> 4;
    if (edge >= nE) return;
    int lane = gid & 15;

    float4 e4 = ef[edge];                  // same addr for 16 lanes -> bcast
    int s = src[edge];
    int d = dst[edge];
    float4 hv = *reinterpret_cast<const float4*>(h + s * HIDDEN + lane * 4);

    float4 w0 = Wes[0][lane], w1 = Wes[1][lane], w2 = Wes[2][lane], w3 = Wes[3][lane];
    float4 b  = bes[lane];

    float4 m;
    m.x = fmaxf(hv.x + b.x + e4.x * w0.x + e4.y * w1.x + e4.z * w2.x + e4.w * w3.x, 0.f);
    m.y = fmaxf(hv.y + b.y + e4.x * w0.y + e4.y * w1.y + e4.z * w2.y + e4.w * w3.y, 0.f);
    m.z = fmaxf(hv.z + b.z + e4.x * w0.z + e4.y * w1.z + e4.z * w2.z + e4.w * w3.z, 0.f);
    m.w = fmaxf(hv.w + b.w + e4.x * w0.w + e4.y * w1.w + e4.z * w2.w + e4.w * w3.w, 0.f);

    float* ap = g_scratch + d * HIDDEN + lane * 4;
    asm volatile("red.global.add.v4.f32 [%0], {%1, %2, %3, %4};"
                 :: "l"(ap), "f"(m.x), "f"(m.y), "f"(m.z), "f"(m.w)
                 : "memory");
}

// ---------------------------------------------------------------------------
// MLP: u = relu(z@W1 + b1)@W2 + b2, z read from scratch, u written back.
// One 64-thread block handles 64 rows (thread = row). Weights + z tile staged
// in shared (z tile padded to 65 floats/row for conflict-free column access).
// Inner products via packed fma.rn.f32x2 (2 fp32 FMA / instr, exact fp32).
// Fuses batch-stat partial reduction (block colsum/colsumsq -> global atomics).
// ---------------------------------------------------------------------------
__global__ __launch_bounds__(64) void mlp_kernel(const float* __restrict__ W1,
                                                 const float* __restrict__ b1,
                                                 const float* __restrict__ W2,
                                                 const float* __restrict__ b2,
                                                 int layer, int n) {
    __shared__ float Ws[64 * 64];
    __shared__ float Zs[64 * 65];
    __shared__ float bs[64];
    int t = threadIdx.x;
    int row0 = blockIdx.x * 64;
    const float4* W1l4 = reinterpret_cast<const float4*>(W1 + layer * 4096);
    const float4* W2l4 = reinterpret_cast<const float4*>(W2 + layer * 4096);
    float4* Ws4 = reinterpret_cast<float4*>(Ws);

    // Stage W1 + b1 + z tile
    #pragma unroll
    for (int i = 0; i < 16; i++) Ws4[i * 64 + t] = W1l4[i * 64 + t];
    bs[t] = b1[layer * 64 + t];

    if (row0 + 64 <= n) {
        // Full tile: vectorized staging (16 x LDG.128 per thread)
        const float4* zg = reinterpret_cast<const float4*>(g_scratch + (size_t)row0 * HIDDEN);
        #pragma unroll
        for (int i = 0; i < 16; i++) {
            int f = i * 64 + t;
            float4 v = zg[f];
            int r = f >> 4;
            float* p = &Zs[r * 65 + (f & 15) * 4];
            p[0] = v.x; p[1] = v.y; p[2] = v.z; p[3] = v.w;
        }
    } else {
        for (int r = 0; r < 64; r++) {
            int rr = row0 + r;
            Zs[r * 65 + t] = (rr < n) ? g_scratch[rr * HIDDEN + t] : 0.f;
        }
    }
    __syncthreads();

    bool valid = (row0 + t) < n;
    unsigned long long acc[32];   // 32 packed f32x2 accumulators = 64 columns
    const float2* bs2 = reinterpret_cast<const float2*>(bs);
    #pragma unroll
    for (int j = 0; j < 32; j++) {
        float2 b = bs2[j];
        asm("mov.b64 %0, {%1, %2};" : "=l"(acc[j]) : "f"(b.x), "f"(b.y));
    }

    // Phase 1: t = relu(z @ W1 + b1)
    for (int k = 0; k < 64; k++) {
        float zk = Zs[t * 65 + k];
        unsigned long long zz;
        asm("mov.b64 %0, {%1, %1};" : "=l"(zz) : "f"(zk));
        const unsigned long long* wr =
            reinterpret_cast<const unsigned long long*>(Ws + k * 64);
        #pragma unroll
        for (int j = 0; j < 32; j++)
            asm("fma.rn.f32x2 %0, %1, %2, %0;" : "+l"(acc[j]) : "l"(zz), "l"(wr[j]));
    }
    // Write relu back into own z row (only self reads it -> no sync needed)
    #pragma unroll
    for (int j = 0; j < 32; j++) {
        float lo, hi;
        asm("mov.b64 {%0, %1}, %2;" : "=f"(lo), "=f"(hi) : "l"(acc[j]));
        Zs[t * 65 + 2 * j]     = fmaxf(lo, 0.f);
        Zs[t * 65 + 2 * j + 1] = fmaxf(hi, 0.f);
    }

    __syncthreads();
    // Stage W2 + b2
    #pragma unroll
    for (int i = 0; i < 16; i++) Ws4[i * 64 + t] = W2l4[i * 64 + t];
    bs[t] = b2[layer * 64 + t];
    __syncthreads();

    #pragma unroll
    for (int j = 0; j < 32; j++) {
        float2 b = bs2[j];
        asm("mov.b64 %0, {%1, %2};" : "=l"(acc[j]) : "f"(b.x), "f"(b.y));
    }

    // Phase 2: u = t @ W2 + b2
    for (int k = 0; k < 64; k++) {
        float tk = Zs[t * 65 + k];
        unsigned long long tt;
        asm("mov.b64 %0, {%1, %1};" : "=l"(tt) : "f"(tk));
        const unsigned long long* wr =
            reinterpret_cast<const unsigned long long*>(Ws + k * 64);
        #pragma unroll
        for (int j = 0; j < 32; j++)
            asm("fma.rn.f32x2 %0, %1, %2, %0;" : "+l"(acc[j]) : "l"(tt), "l"(wr[j]));
    }
    __syncthreads();   // everyone done reading Zs (phase-2 t values)

    // Put u into own Zs row (zeros for invalid rows so stats stay clean)
    #pragma unroll
    for (int j = 0; j < 32; j++) {
        float lo, hi;
        asm("mov.b64 {%0, %1}, %2;" : "=f"(lo), "=f"(hi) : "l"(acc[j]));
        Zs[t * 65 + 2 * j]     = valid ? lo : 0.f;
        Zs[t * 65 + 2 * j + 1] = valid ? hi : 0.f;
    }
    __syncthreads();

    // Coalesced store of u to scratch
    for (int r = 0; r < 64; r++) {
        int rr = row0 + r;
        if (rr < n) g_scratch[rr * HIDDEN + t] = Zs[r * 65 + t];
    }

    // Block-level column stats, one atomic pair per column per block
    float s = 0.f, sq = 0.f;
    for (int r = 0; r < 64; r++) {
        float v = Zs[r * 65 + t];
        s += v;
        sq += v * v;
    }
    atomicAdd(&g_stats[layer * 128 + t], s);
    atomicAdd(&g_stats[layer * 128 + 64 + t], sq);
}

// ---------------------------------------------------------------------------
// BN + ReLU + residual: h = relu(gamma*(u-mu)*istd + beta) + h.
// Writes h (d_out) in place; also refreshes scratch = h_new for the next
// layer's aggregation (skipped on last layer).
// ---------------------------------------------------------------------------
__global__ void bn_kernel(float4* __restrict__ h,
                          const float* __restrict__ gamma,
                          const float* __restrict__ beta,
                          int layer, int n4, float invN, int last) {
    int i = blockIdx.x * blockDim.x + threadIdx.x;
    if (i >= n4) return;
    int j = (i & 15) * 4;
    const float* st = g_stats + layer * 128;
    const float* g  = gamma + layer * 64;
    const float* be = beta + layer * 64;

    float4 u  = reinterpret_cast<const float4*>(g_scratch)[i];
    float4 hv = h[i];
    float4 r;

    #define BN_COMP(comp, jj)                                              \
    {                                                                      \
        float mu  = st[jj] * invN;                                         \
        float var = st[64 + jj] * invN - mu * mu;                          \
        float z   = g[jj] * (u.comp - mu) * rsqrtf(var + BN_EPS) + be[jj]; \
        r.comp    = fmaxf(z, 0.f) + hv.comp;                               \
    }
    BN_COMP(x, j + 0)
    BN_COMP(y, j + 1)
    BN_COMP(z, j + 2)
    BN_COMP(w, j + 3)
    #undef BN_COMP

    h[i] = r;
    if (!last) reinterpret_cast<float4*>(g_scratch)[i] = r;
}

// ---------------------------------------------------------------------------
extern "C" void kernel_launch(void* const* d_in, const int* in_sizes, int n_in,
                              void* d_out, int out_size) {
    const float*  node  = (const float*)d_in[0];
    const float4* ef    = (const float4*)d_in[1];
    const int*    src   = (const int*)d_in[2];
    const int*    dst   = (const int*)d_in[3];
    const float*  We    = (const float*)d_in[4];
    const float*  be    = (const float*)d_in[5];
    const float*  W1    = (const float*)d_in[6];
    const float*  b1    = (const float*)d_in[7];
    const float*  W2    = (const float*)d_in[8];
    const float*  b2    = (const float*)d_in[9];
    const float*  gamma = (const float*)d_in[10];
    const float*  beta  = (const float*)d_in[11];

    float* h = (float*)d_out;
    int n  = in_sizes[0] / HIDDEN;   // 100000
    int nE = in_sizes[2];            // 1600000
    int n4 = n * (HIDDEN / 4);
    float invN = 1.f / (float)n;

    init_kernel<<<(n4 + 255) / 256, 256>>>((float4*)h, (const float4*)node, n4);

    for (int l = 0; l < N_LAYERS; l++) {
        int egrid = (nE * 16 + 255) / 256;
        edge_kernel<<<egrid, 256>>>(h, ef, src, dst, We, be, nE);
        mlp_kernel<<<(n + 63) / 64, 64>>>(W1, b1, W2, b2, l, n);
        bn_kernel<<<(n4 + 255) / 256, 256>>>((float4*)h, gamma, beta, l, n4,
                                             invN, l == N_LAYERS - 1);
    }
}

// round 3
// speedup vs baseline: 1.3837x; 1.3442x over previous
#include <cuda_runtime.h>

#define HIDDEN 64
#define N_LAYERS 4
#define BN_EPS 1e-5f
#define MAX_NODES 100000
#define MAX_EDGES 1600000

// Scratch: z -> u per layer. 25.6 MB.
__device__ __align__(16) float g_scratch[MAX_NODES * HIDDEN];
// Per-layer batch-norm stats: [layer][0:64]=colsum, [layer][64:128]=colsumsq
__device__ float g_stats[N_LAYERS * 128];
// CSR-by-dst structures (built once per launch)
__device__ int   g_deg[MAX_NODES];
__device__ int   g_rowstart[MAX_NODES + 1];
__device__ int   g_cursor[MAX_NODES];
__device__ int   g_bsum[128];
__device__ int   g_bsumx[128];
__device__ int   g_csr_src[MAX_EDGES];
__device__ __align__(16) float4 g_csr_ef[MAX_EDGES];

// ---------------------------------------------------------------------------
// Init: h = node_feat, zero stats + degree histogram.
// ---------------------------------------------------------------------------
__global__ void init_kernel(float4* __restrict__ h,
                            const float4* __restrict__ node,
                            int n4, int n) {
    int i = blockIdx.x * blockDim.x + threadIdx.x;
    if (i < N_LAYERS * 128) g_stats[i] = 0.f;
    if (i < n) g_deg[i] = 0;
    if (i < n4) h[i] = node[i];
}

// ---------------------------------------------------------------------------
// CSR build: histogram, 3-phase exclusive scan, scatter.
// ---------------------------------------------------------------------------
__global__ void hist_kernel(const int* __restrict__ dst, int nE) {
    int i = blockIdx.x * blockDim.x + threadIdx.x;
    if (i < nE) atomicAdd(&g_deg[dst[i]], 1);
}

__global__ void scan1_kernel(int n) {
    __shared__ int s[1024];
    int t = threadIdx.x;
    int i = blockIdx.x * 1024 + t;
    int v = (i < n) ? g_deg[i] : 0;
    s[t] = v;
    __syncthreads();
    for (int off = 1; off < 1024; off <<= 1) {
        int y = (t >= off) ? s[t - off] : 0;
        __syncthreads();
        s[t] += y;
        __syncthreads();
    }
    if (i < n) g_rowstart[i] = s[t] - v;         // exclusive within block
    if (t == 1023) g_bsum[blockIdx.x] = s[1023]; // block total
}

__global__ void scan2_kernel(int nb) {
    __shared__ int s[128];
    int t = threadIdx.x;
    int v = (t < nb) ? g_bsum[t] : 0;
    s[t] = v;
    __syncthreads();
    for (int off = 1; off < 128; off <<= 1) {
        int y = (t >= off) ? s[t - off] : 0;
        __syncthreads();
        s[t] += y;
        __syncthreads();
    }
    if (t < nb) g_bsumx[t] = s[t] - v;           // exclusive over blocks
}

__global__ void scan3_kernel(int n, int nE) {
    int i = blockIdx.x * blockDim.x + threadIdx.x;
    if (i < n) {
        int r = g_rowstart[i] + g_bsumx[i >> 10];
        g_rowstart[i] = r;
        g_cursor[i] = r;
    }
    if (i == 0) g_rowstart[n] = nE;
}

__global__ void scatter_kernel(const int* __restrict__ src,
                               const int* __restrict__ dst,
                               const float4* __restrict__ ef,
                               int nE) {
    int i = blockIdx.x * blockDim.x + threadIdx.x;
    if (i >= nE) return;
    int d = dst[i];
    int p = atomicAdd(&g_cursor[d], 1);
    g_csr_src[p] = src[i];
    g_csr_ef[p] = ef[i];
}

// ---------------------------------------------------------------------------
// Aggregation (no atomics): z[node] = h[node] + sum_{in-edges} relu(h[src]+e),
// e = ef@We + be recomputed on the fly. 16 threads/node, float4 accumulators.
// Writes z into scratch.
// ---------------------------------------------------------------------------
__global__ __launch_bounds__(256) void agg_kernel(const float* __restrict__ h,
                                                  const float* __restrict__ We,
                                                  const float* __restrict__ be,
                                                  int n) {
    __shared__ float4 Wes[4][16];
    __shared__ float4 bes[16];
    int t = threadIdx.x;
    if (t < 256) reinterpret_cast<float*>(Wes)[t] = We[t];
    if (t < 64)  reinterpret_cast<float*>(bes)[t] = be[t];
    __syncthreads();

    int gid = blockIdx.x * blockDim.x + t;
    int node = gid >> 4;
    if (node >= n) return;
    int lane = gid & 15;

    float4 w0 = Wes[0][lane], w1 = Wes[1][lane], w2 = Wes[2][lane], w3 = Wes[3][lane];
    float4 b  = bes[lane];

    float4 acc = *reinterpret_cast<const float4*>(h + node * HIDDEN + lane * 4);
    int p0 = g_rowstart[node], p1 = g_rowstart[node + 1];

    for (int p = p0; p < p1; p++) {
        int s = g_csr_src[p];
        float4 e4 = g_csr_ef[p];
        float4 hv = *reinterpret_cast<const float4*>(h + s * HIDDEN + lane * 4);
        acc.x += fmaxf(hv.x + b.x + e4.x * w0.x + e4.y * w1.x + e4.z * w2.x + e4.w * w3.x, 0.f);
        acc.y += fmaxf(hv.y + b.y + e4.x * w0.y + e4.y * w1.y + e4.z * w2.y + e4.w * w3.y, 0.f);
        acc.z += fmaxf(hv.z + b.z + e4.x * w0.z + e4.y * w1.z + e4.z * w2.z + e4.w * w3.z, 0.f);
        acc.w += fmaxf(hv.w + b.w + e4.x * w0.w + e4.y * w1.w + e4.z * w2.w + e4.w * w3.w, 0.f);
    }

    *reinterpret_cast<float4*>(g_scratch + node * HIDDEN + lane * 4) = acc;
}

// ---------------------------------------------------------------------------
// MLP: u = relu(z@W1 + b1)@W2 + b2, z read from scratch, u written back.
// One 64-thread block handles 64 rows (thread = row). Packed fma.rn.f32x2.
// Fuses batch-stat partial reduction.
// ---------------------------------------------------------------------------
__global__ __launch_bounds__(64) void mlp_kernel(const float* __restrict__ W1,
                                                 const float* __restrict__ b1,
                                                 const float* __restrict__ W2,
                                                 const float* __restrict__ b2,
                                                 int layer, int n) {
    __shared__ float Ws[64 * 64];
    __shared__ float Zs[64 * 65];
    __shared__ float bs[64];
    int t = threadIdx.x;
    int row0 = blockIdx.x * 64;
    const float4* W1l4 = reinterpret_cast<const float4*>(W1 + layer * 4096);
    const float4* W2l4 = reinterpret_cast<const float4*>(W2 + layer * 4096);
    float4* Ws4 = reinterpret_cast<float4*>(Ws);

    #pragma unroll
    for (int i = 0; i < 16; i++) Ws4[i * 64 + t] = W1l4[i * 64 + t];
    bs[t] = b1[layer * 64 + t];

    if (row0 + 64 <= n) {
        const float4* zg = reinterpret_cast<const float4*>(g_scratch + (size_t)row0 * HIDDEN);
        #pragma unroll
        for (int i = 0; i < 16; i++) {
            int f = i * 64 + t;
            float4 v = zg[f];
            int r = f >> 4;
            float* p = &Zs[r * 65 + (f & 15) * 4];
            p[0] = v.x; p[1] = v.y; p[2] = v.z; p[3] = v.w;
        }
    } else {
        for (int r = 0; r < 64; r++) {
            int rr = row0 + r;
            Zs[r * 65 + t] = (rr < n) ? g_scratch[rr * HIDDEN + t] : 0.f;
        }
    }
    __syncthreads();

    bool valid = (row0 + t) < n;
    unsigned long long acc[32];
    const float2* bs2 = reinterpret_cast<const float2*>(bs);
    #pragma unroll
    for (int j = 0; j < 32; j++) {
        float2 b = bs2[j];
        asm("mov.b64 %0, {%1, %2};" : "=l"(acc[j]) : "f"(b.x), "f"(b.y));
    }

    for (int k = 0; k < 64; k++) {
        float zk = Zs[t * 65 + k];
        unsigned long long zz;
        asm("mov.b64 %0, {%1, %1};" : "=l"(zz) : "f"(zk));
        const unsigned long long* wr =
            reinterpret_cast<const unsigned long long*>(Ws + k * 64);
        #pragma unroll
        for (int j = 0; j < 32; j++)
            asm("fma.rn.f32x2 %0, %1, %2, %0;" : "+l"(acc[j]) : "l"(zz), "l"(wr[j]));
    }
    #pragma unroll
    for (int j = 0; j < 32; j++) {
        float lo, hi;
        asm("mov.b64 {%0, %1}, %2;" : "=f"(lo), "=f"(hi) : "l"(acc[j]));
        Zs[t * 65 + 2 * j]     = fmaxf(lo, 0.f);
        Zs[t * 65 + 2 * j + 1] = fmaxf(hi, 0.f);
    }

    __syncthreads();
    #pragma unroll
    for (int i = 0; i < 16; i++) Ws4[i * 64 + t] = W2l4[i * 64 + t];
    bs[t] = b2[layer * 64 + t];
    __syncthreads();

    #pragma unroll
    for (int j = 0; j < 32; j++) {
        float2 b = bs2[j];
        asm("mov.b64 %0, {%1, %2};" : "=l"(acc[j]) : "f"(b.x), "f"(b.y));
    }

    for (int k = 0; k < 64; k++) {
        float tk = Zs[t * 65 + k];
        unsigned long long tt;
        asm("mov.b64 %0, {%1, %1};" : "=l"(tt) : "f"(tk));
        const unsigned long long* wr =
            reinterpret_cast<const unsigned long long*>(Ws + k * 64);
        #pragma unroll
        for (int j = 0; j < 32; j++)
            asm("fma.rn.f32x2 %0, %1, %2, %0;" : "+l"(acc[j]) : "l"(tt), "l"(wr[j]));
    }
    __syncthreads();

    #pragma unroll
    for (int j = 0; j < 32; j++) {
        float lo, hi;
        asm("mov.b64 {%0, %1}, %2;" : "=f"(lo), "=f"(hi) : "l"(acc[j]));
        Zs[t * 65 + 2 * j]     = valid ? lo : 0.f;
        Zs[t * 65 + 2 * j + 1] = valid ? hi : 0.f;
    }
    __syncthreads();

    for (int r = 0; r < 64; r++) {
        int rr = row0 + r;
        if (rr < n) g_scratch[rr * HIDDEN + t] = Zs[r * 65 + t];
    }

    float s = 0.f, sq = 0.f;
    for (int r = 0; r < 64; r++) {
        float v = Zs[r * 65 + t];
        s += v;
        sq += v * v;
    }
    atomicAdd(&g_stats[layer * 128 + t], s);
    atomicAdd(&g_stats[layer * 128 + 64 + t], sq);
}

// ---------------------------------------------------------------------------
// BN + ReLU + residual: h = relu(gamma*(u-mu)*istd + beta) + h (h only).
// ---------------------------------------------------------------------------
__global__ void bn_kernel(float4* __restrict__ h,
                          const float* __restrict__ gamma,
                          const float* __restrict__ beta,
                          int layer, int n4, float invN) {
    int i = blockIdx.x * blockDim.x + threadIdx.x;
    if (i >= n4) return;
    int j = (i & 15) * 4;
    const float* st = g_stats + layer * 128;
    const float* g  = gamma + layer * 64;
    const float* be = beta + layer * 64;

    float4 u  = reinterpret_cast<const float4*>(g_scratch)[i];
    float4 hv = h[i];
    float4 r;

    #define BN_COMP(comp, jj)                                              \
    {                                                                      \
        float mu  = st[jj] * invN;                                         \
        float var = st[64 + jj] * invN - mu * mu;                          \
        float z   = g[jj] * (u.comp - mu) * rsqrtf(var + BN_EPS) + be[jj]; \
        r.comp    = fmaxf(z, 0.f) + hv.comp;                               \
    }
    BN_COMP(x, j + 0)
    BN_COMP(y, j + 1)
    BN_COMP(z, j + 2)
    BN_COMP(w, j + 3)
    #undef BN_COMP

    h[i] = r;
}

// ---------------------------------------------------------------------------
extern "C" void kernel_launch(void* const* d_in, const int* in_sizes, int n_in,
                              void* d_out, int out_size) {
    const float*  node  = (const float*)d_in[0];
    const float4* ef    = (const float4*)d_in[1];
    const int*    src   = (const int*)d_in[2];
    const int*    dst   = (const int*)d_in[3];
    const float*  We    = (const float*)d_in[4];
    const float*  be    = (const float*)d_in[5];
    const float*  W1    = (const float*)d_in[6];
    const float*  b1    = (const float*)d_in[7];
    const float*  W2    = (const float*)d_in[8];
    const float*  b2    = (const float*)d_in[9];
    const float*  gamma = (const float*)d_in[10];
    const float*  beta  = (const float*)d_in[11];

    float* h = (float*)d_out;
    int n  = in_sizes[0] / HIDDEN;   // 100000
    int nE = in_sizes[2];            // 1600000
    int n4 = n * (HIDDEN / 4);
    float invN = 1.f / (float)n;
    int nb = (n + 1023) / 1024;

    init_kernel<<<(n4 + 255) / 256, 256>>>((float4*)h, (const float4*)node, n4, n);

    // CSR build (once per launch)
    hist_kernel<<<(nE + 255) / 256, 256>>>(dst, nE);
    scan1_kernel<<<nb, 1024>>>(n);
    scan2_kernel<<<1, 128>>>(nb);
    scan3_kernel<<<(n + 255) / 256, 256>>>(n, nE);
    scatter_kernel<<<(nE + 255) / 256, 256>>>(src, dst, ef, nE);

    for (int l = 0; l < N_LAYERS; l++) {
        int agrid = (n * 16 + 255) / 256;
        agg_kernel<<<agrid, 256>>>(h, We, be, n);
        mlp_kernel<<<(n + 63) / 64, 64>>>(W1, b1, W2, b2, l, n);
        bn_kernel<<<(n4 + 255) / 256, 256>>>((float4*)h, gamma, beta, l, n4, invN);
    }
}